// round 16
// baseline (speedup 1.0000x reference)
#include <cuda_runtime.h>
#include <stdint.h>

// RadarDopSparseProcessor — exact 0.9-quantile radix select:
// pass1 = 12-bit hist (+select tail), pass2 = 12-bit mid hist + candidate
// collect (+select tail), pass3 = tiny 8-bit hist over candidates (+thr tail).
// Then ordered lookback stream compaction (R13-proven) + tail cleanup.

#define Bn 4
#define Zd 40
#define Yd 320
#define Xd 320
#define Nv (Zd*Yd*Xd)            // 4,096,000
#define Kpad (Nv/10 + 64)        // 409,664
#define BKr (Bn*Kpad)            // 1,638,656
#define VPBATCH (Nv/4)           // 1,024,000 float4 per batch

#define HV_BLOCKS 37
#define VPB 27676                // ceil(1024000/37)
#define H3C_BLOCKS 8
#define SC_BLOCKS 250
#define SC_THREADS 512
#define SENT 0xFFFFFFFFu
#define MAXC Nv

__device__ unsigned g_hist1[Bn][4096];
__device__ unsigned g_hist2[Bn][2][4096];
__device__ unsigned g_hist3[Bn][2][256];
__device__ unsigned g_s1[Bn][4];          // selA, remA, selB, remB
__device__ unsigned g_s2[Bn][4];          // sel2A, rem2A, sel2B, rem2B
__device__ unsigned g_ccnt[Bn];
__device__ unsigned g_cand[Bn][MAXC];
__device__ float    g_thr[Bn];
__device__ unsigned g_done1[Bn];
__device__ unsigned g_done2[Bn];
__device__ unsigned g_done3[Bn];
__device__ unsigned long long g_part[Bn][SC_BLOCKS];
__device__ unsigned g_total[Bn];

__device__ __forceinline__ unsigned wscan(unsigned v, int lane){
  #pragma unroll
  for (int d=1; d<32; d<<=1){
    unsigned n = __shfl_up_sync(0xFFFFFFFFu, v, d);
    if (lane >= d) v += n;
  }
  return v;
}

__device__ __forceinline__ void qranks(unsigned& R0, unsigned& R1){
  const float QPOS = 0.9f * (float)(Nv-1);
  R0 = (unsigned)floorf(QPOS);
  R1 = (unsigned)ceilf(QPOS); if (R1 > Nv-1) R1 = Nv-1;
}

__global__ __launch_bounds__(1024) void k_zero(){
  int i = blockIdx.x*1024 + threadIdx.x;
  if (i < Bn*4096)      (&g_hist1[0][0])[i] = 0u;
  if (i < Bn*2*4096)    (&g_hist2[0][0][0])[i] = 0u;
  if (i < Bn*2*256)     (&g_hist3[0][0][0])[i] = 0u;
  if (i < Bn*SC_BLOCKS) (&g_part[0][0])[i] = 0ull;
  if (i < Bn){ g_done1[i]=0u; g_done2[i]=0u; g_done3[i]=0u; g_ccnt[i]=0u; g_total[i]=0u; }
}

// ---- block-collective select over a 4096-bin smem histogram (1024 threads) ----
__device__ void bsel4096(const unsigned* h, unsigned rA, unsigned rB,
                         unsigned* swq, unsigned* res){
  int tid=threadIdx.x, lane=tid&31;
  unsigned l0=h[tid*4+0],l1=h[tid*4+1],l2=h[tid*4+2],l3=h[tid*4+3];
  unsigned sum=l0+l1+l2+l3;
  unsigned inc=wscan(sum,lane);
  if (lane==31) swq[tid>>5]=inc;
  __syncthreads();
  if (tid==0){unsigned run=0; for(int k=0;k<32;k++){unsigned t=swq[k];swq[k]=run;run+=t;}}
  __syncthreads();
  unsigned excl=inc-sum+swq[tid>>5];
  unsigned rr[2]={rA,rB};
  #pragma unroll
  for (int j=0;j<2;j++){
    unsigned r=rr[j];
    if (r!=SENT && r>=excl && r<excl+sum){
      unsigned c=excl; unsigned loc[4]={l0,l1,l2,l3};
      #pragma unroll
      for (int k=0;k<4;k++){
        if (r < c+loc[k]){ res[2*j]=(unsigned)(tid*4+k); res[2*j+1]=r-c; break; }
        c+=loc[k];
      }
    }
  }
  __syncthreads();
}

__device__ void bsel256(const unsigned* h, unsigned rA, unsigned rB,
                        unsigned* swq, unsigned* res){
  int tid=threadIdx.x, lane=tid&31;
  int nthr=blockDim.x;
  unsigned v=0, inc=0;
  if (tid<256){ v=h[tid]; inc=wscan(v,lane); }
  if (tid<256 && lane==31) swq[tid>>5]=inc;
  __syncthreads();
  if (tid==0){unsigned run=0; for(int k=0;k<8;k++){unsigned t=swq[k];swq[k]=run;run+=t;}}
  __syncthreads();
  if (tid<256){
    unsigned excl=inc-v+swq[tid>>5];
    unsigned rr[2]={rA,rB};
    #pragma unroll
    for (int j=0;j<2;j++){
      unsigned r=rr[j];
      if (r!=SENT && r>=excl && r<excl+v) res[2*j]=(unsigned)tid;
    }
  }
  __syncthreads();
  (void)nthr;
}

// ---- last-block detection (threadFenceReduction pattern) ----
__device__ __forceinline__ bool last_block(unsigned* ctr, unsigned total, bool* sflag){
  __threadfence();
  __syncthreads();
  if (threadIdx.x==0) *sflag = (atomicAdd(ctr,1u) == total-1u);
  __syncthreads();
  return *sflag;
}

// ---------------- pass 1: 12-bit histogram, 2-way replicated smem ----------------
__device__ __forceinline__ void h1a(unsigned* h, float4 a){
  atomicAdd(&h[__float_as_uint(a.x)>>20],1u);
  atomicAdd(&h[__float_as_uint(a.y)>>20],1u);
  atomicAdd(&h[__float_as_uint(a.z)>>20],1u);
  atomicAdd(&h[__float_as_uint(a.w)>>20],1u);
}
__global__ __launch_bounds__(1024) void k_hist1(const float* __restrict__ cube){
  __shared__ unsigned hist[2][4096];
  __shared__ unsigned swq[32];
  __shared__ unsigned sres[4];
  __shared__ bool sflag;
  int b = blockIdx.y, tid = threadIdx.x;
  unsigned* myh = hist[(tid>>5)&1];
  int start = blockIdx.x * VPB;
  int n = min(VPB, VPBATCH - start);
  const float4* p = (const float4*)cube + (size_t)b*VPBATCH + start;
  for (int i=tid;i<8192;i+=1024) (&hist[0][0])[i]=0u;
  __syncthreads();
  int i = tid;
  for (; i + 3072 < n; i += 4096){
    float4 v0=p[i], v1=p[i+1024], v2=p[i+2048], v3=p[i+3072];
    h1a(myh,v0); h1a(myh,v1); h1a(myh,v2); h1a(myh,v3);
  }
  for (; i < n; i += 1024) h1a(myh, p[i]);
  __syncthreads();
  for (int k=tid;k<4096;k+=1024){
    unsigned c=hist[0][k]+hist[1][k];
    if (c) atomicAdd(&g_hist1[b][k], c);
  }
  if (last_block(&g_done1[b], HV_BLOCKS, &sflag)){
    for (int k=tid;k<4096;k+=1024) hist[0][k]=__ldcg(&g_hist1[b][k]);
    __syncthreads();
    unsigned R0,R1; qranks(R0,R1);
    bsel4096(hist[0], R0, R1, swq, sres);
    if (tid<4) g_s1[b][tid]=sres[tid];
  }
}

// ---------------- pass 2: 12-bit mid histogram + candidate collect ----------------
__global__ __launch_bounds__(1024) void k_hist2(const float* __restrict__ cube){
  __shared__ unsigned hist[2][4096];
  __shared__ unsigned swq[32];
  __shared__ unsigned swb[32];
  __shared__ unsigned sres[4];
  __shared__ unsigned sbase;
  __shared__ bool sflag;
  int b = blockIdx.y, tid = threadIdx.x, lane = tid&31, wid = tid>>5;
  unsigned sa=__ldcg(&g_s1[b][0]);
  unsigned sb=__ldcg(&g_s1[b][2]);
  for (int i=tid;i<8192;i+=1024) (&hist[0][0])[i]=0u;
  __syncthreads();
  int start = blockIdx.x * VPB;
  int n = min(VPB, VPBATCH - start);
  const float4* p = (const float4*)cube + (size_t)b*VPBATCH + start;

  for (int t0=0; t0<n; t0+=4096){
    float4 v[4]; bool ok[4];
    unsigned mc=0;
    #pragma unroll
    for (int j=0;j<4;j++){
      int idx=t0+j*1024+tid;
      ok[j]=(idx<n);
      if (ok[j]) v[j]=p[idx];
    }
    #pragma unroll
    for (int j=0;j<4;j++){
      if (ok[j]){
        float vv[4]={v[j].x,v[j].y,v[j].z,v[j].w};
        #pragma unroll
        for (int c2=0;c2<4;c2++){
          unsigned u=__float_as_uint(vv[c2]); unsigned t=u>>20;
          if (t==sa){ atomicAdd(&hist[0][(u>>8)&0xFFFu],1u); mc++; }
          else if (t==sb){ atomicAdd(&hist[1][(u>>8)&0xFFFu],1u); mc++; }
        }
      }
    }
    unsigned inc=wscan(mc,lane);
    if (lane==31) swq[wid]=inc;
    __syncthreads();
    if (tid==0){
      unsigned run=0;
      for (int k=0;k<32;k++){unsigned t=swq[k]; swb[k]=run; run+=t;}
      sbase = run ? atomicAdd(&g_ccnt[b], run) : 0u;
    }
    __syncthreads();
    unsigned pos = sbase + swb[wid] + inc - mc;
    #pragma unroll
    for (int j=0;j<4;j++){
      if (ok[j]){
        float vv[4]={v[j].x,v[j].y,v[j].z,v[j].w};
        #pragma unroll
        for (int c2=0;c2<4;c2++){
          unsigned u=__float_as_uint(vv[c2]); unsigned t=u>>20;
          if (t==sa || t==sb) g_cand[b][pos++]=u;
        }
      }
    }
    __syncthreads();
  }
  for (int k=tid;k<8192;k+=1024){
    unsigned c=(&hist[0][0])[k];
    if (c) atomicAdd((&g_hist2[b][0][0])+k, c);
  }
  if (last_block(&g_done2[b], HV_BLOCKS, &sflag)){
    unsigned selA=__ldcg(&g_s1[b][0]), remA=__ldcg(&g_s1[b][1]);
    unsigned selB=__ldcg(&g_s1[b][2]), remB=__ldcg(&g_s1[b][3]);
    unsigned sel2A, rem2A, sel2B, rem2B;
    for (int k=tid;k<4096;k+=1024) hist[0][k]=__ldcg(&g_hist2[b][0][k]);
    __syncthreads();
    if (selA==selB){
      bsel4096(hist[0], remA, remB, swq, sres);
      sel2A=(selA<<12)|sres[0]; rem2A=sres[1];
      sel2B=(selB<<12)|sres[2]; rem2B=sres[3];
    } else {
      bsel4096(hist[0], remA, SENT, swq, sres);
      sel2A=(selA<<12)|sres[0]; rem2A=sres[1];
      __syncthreads();
      for (int k=tid;k<4096;k+=1024) hist[0][k]=__ldcg(&g_hist2[b][1][k]);
      __syncthreads();
      bsel4096(hist[0], SENT, remB, swq, sres);
      sel2B=(selB<<12)|sres[2]; rem2B=sres[3];
    }
    if (tid==0){ g_s2[b][0]=sel2A; g_s2[b][1]=rem2A; g_s2[b][2]=sel2B; g_s2[b][3]=rem2B; }
  }
}

// ---------------- pass 3: 8-bit histogram over candidates (tiny) ----------------
__global__ __launch_bounds__(1024) void k_hist3c(){
  __shared__ unsigned h8[512];
  __shared__ unsigned swq[32];
  __shared__ unsigned sres[4];
  __shared__ bool sflag;
  int b = blockIdx.y, tid = threadIdx.x;
  unsigned p0=__ldcg(&g_s2[b][0]);
  unsigned p1=__ldcg(&g_s2[b][2]);
  for (int i=tid;i<512;i+=1024) h8[i]=0u;
  __syncthreads();
  unsigned cc = __ldcg(&g_ccnt[b]);
  unsigned slice = (cc + H3C_BLOCKS-1u)/H3C_BLOCKS;
  unsigned i0 = (unsigned)blockIdx.x*slice;
  unsigned i1 = min(i0+slice, cc);
  for (unsigned base=i0; base<i1; base+=8192u){
    unsigned u[8]; bool m[8];
    #pragma unroll
    for (int j=0;j<8;j++){
      unsigned idx = base + (unsigned)j*1024u + (unsigned)tid;
      m[j] = (idx < i1);
      u[j] = m[j] ? __ldcg(&g_cand[b][idx]) : 0u;
    }
    #pragma unroll
    for (int j=0;j<8;j++){
      if (m[j]){
        unsigned pre=u[j]>>8;
        if (pre==p0) atomicAdd(&h8[u[j]&0xFFu],1u);
        else if (pre==p1) atomicAdd(&h8[256u+(u[j]&0xFFu)],1u);
      }
    }
  }
  __syncthreads();
  for (int k=tid;k<512;k+=1024){
    unsigned c=h8[k];
    if (c) atomicAdd((&g_hist3[b][0][0])+k, c);
  }
  if (last_block(&g_done3[b], H3C_BLOCKS, &sflag)){
    unsigned sel2A=__ldcg(&g_s2[b][0]), rem2A=__ldcg(&g_s2[b][1]);
    unsigned sel2B=__ldcg(&g_s2[b][2]), rem2B=__ldcg(&g_s2[b][3]);
    for (int k=tid;k<512;k+=1024) h8[k]=__ldcg((&g_hist3[b][0][0])+k);
    __syncthreads();
    unsigned binA, binB;
    if (sel2A==sel2B){
      bsel256(&h8[0], rem2A, rem2B, swq, sres);
      binA=sres[0]; binB=sres[2];
    } else {
      bsel256(&h8[0], rem2A, SENT, swq, sres);
      binA=sres[0];
      __syncthreads();
      bsel256(&h8[256], SENT, rem2B, swq, sres);
      binB=sres[2];
    }
    if (tid==0){
      const float QPOS = 0.9f * (float)(Nv-1);
      float frac = QPOS - floorf(QPOS);
      float va=__uint_as_float((sel2A<<8)|binA);
      float vb=__uint_as_float((sel2B<<8)|binB);
      g_thr[b]=va*(1.0f-frac)+vb*frac;
    }
  }
}

// ---------------- fused compaction with decoupled lookback (R13-proven) ----------------
__global__ __launch_bounds__(SC_THREADS) void k_scatter(const float* __restrict__ cube,
                                                        const float* __restrict__ dop,
                                                        float* __restrict__ out, int out_elems){
  __shared__ unsigned warpsum[16];
  __shared__ unsigned warpexcl[16];
  __shared__ unsigned s_agg;
  __shared__ unsigned s_gexcl;
  int b = blockIdx.y;
  float thr = g_thr[b];
  int tid = threadIdx.x, lane = tid & 31, wid = tid >> 5;

  unsigned gvec0 = (unsigned)blockIdx.x*4096u + (unsigned)wid*256u;
  const float4* p = (const float4*)cube + (size_t)b*VPBATCH + gvec0;

  float4 v[8];
  #pragma unroll
  for (int j=0;j<8;j++) v[j] = p[j*32 + lane];

  unsigned esc[8], gbase[8];
  unsigned run = 0;
  #pragma unroll
  for (int j=0;j<8;j++){
    unsigned c = (v[j].x>thr)+(v[j].y>thr)+(v[j].z>thr)+(v[j].w>thr);
    unsigned inc = c;
    #pragma unroll
    for (int d=1;d<32;d<<=1){ unsigned t=__shfl_up_sync(0xFFFFFFFFu,inc,d); if (lane>=d) inc+=t; }
    esc[j] = inc - c;
    gbase[j] = run;
    run += __shfl_sync(0xFFFFFFFFu, inc, 31);
  }
  if (lane==0) warpsum[wid] = run;
  __syncthreads();
  if (tid==0){
    unsigned acc=0;
    for (int k=0;k<16;k++){ unsigned t=warpsum[k]; warpexcl[k]=acc; acc+=t; }
    s_agg = acc;
  }
  __syncthreads();

  if (wid==0){
    unsigned agg = s_agg;
    unsigned excl = 0;
    int bx = blockIdx.x;
    if (bx == 0){
      if (lane==0) atomicExch(&g_part[b][0], (2ull<<62) | (unsigned long long)agg);
    } else {
      if (lane==0) atomicExch(&g_part[b][bx], (1ull<<62) | (unsigned long long)agg);
      unsigned running = 0;
      int j = bx - 1;
      while (true){
        int idx = j - lane;
        unsigned long long w; unsigned st;
        do {
          w = (idx >= 0) ? atomicAdd(&g_part[b][idx], 0ull) : (2ull<<62);
          st = (unsigned)(w>>62);
        } while (__any_sync(0xFFFFFFFFu, st==0u));
        unsigned val = (unsigned)(w & 0xFFFFFFFFull);
        unsigned bal = __ballot_sync(0xFFFFFFFFu, st==2u);
        if (bal){
          int f = __ffs(bal)-1;
          unsigned contrib = (lane<=f) ? val : 0u;
          #pragma unroll
          for (int d=16;d>0;d>>=1) contrib += __shfl_down_sync(0xFFFFFFFFu,contrib,d);
          running += __shfl_sync(0xFFFFFFFFu, contrib, 0);
          break;
        } else {
          unsigned contrib = val;
          #pragma unroll
          for (int d=16;d>0;d>>=1) contrib += __shfl_down_sync(0xFFFFFFFFu,contrib,d);
          running += __shfl_sync(0xFFFFFFFFu, contrib, 0);
          j -= 32;
        }
      }
      excl = running;
      if (lane==0) atomicExch(&g_part[b][bx], (2ull<<62) | (unsigned long long)(excl+agg));
    }
    if (lane==0){
      s_gexcl = excl;
      if (bx == SC_BLOCKS-1) g_total[b] = excl + agg;
    }
  }
  __syncthreads();

  unsigned warpbase = s_gexcl + warpexcl[wid];
  const float* dopb = dop + (size_t)b*Nv;
  const bool fits = (out_elems >= (int)(10u*(unsigned)BKr));
  #pragma unroll
  for (int j=0;j<8;j++){
    unsigned o = warpbase + gbase[j] + esc[j];
    unsigned gvec = gvec0 + (unsigned)j*32u + (unsigned)lane;
    float vals[4] = {v[j].x, v[j].y, v[j].z, v[j].w};
    float dv[4];
    #pragma unroll
    for (int c2=0;c2<4;c2++){
      if (vals[c2] > thr) dv[c2] = __ldg(&dopb[gvec*4u + (unsigned)c2]);
    }
    #pragma unroll
    for (int c2=0;c2<4;c2++){
      if (vals[c2] > thr){
        unsigned gidx = gvec*4u + (unsigned)c2;
        unsigned z = gidx/(Yd*Xd);
        unsigned rem = gidx - z*(Yd*Xd);
        unsigned y = rem/Xd;
        unsigned x = rem - y*Xd;
        unsigned row = (unsigned)b*Kpad + o;
        if (fits){
          unsigned f = row*5u;
          out[f+0u] = ((float)x/320.0f)*72.0f;
          out[f+1u] = ((float)y/320.0f)*32.0f;
          out[f+2u] = ((float)z/40.0f)*8.0f;
          out[f+3u] = vals[c2] / 10000000000000.0f;
          out[f+4u] = dv[c2] - 1.9326f;
          unsigned ioff = 5u*(unsigned)BKr + row*4u;
          float4 iv = make_float4((float)b,(float)z,(float)y,(float)x);
          *reinterpret_cast<float4*>(out + ioff) = iv;   // 16B-aligned
          out[9u*(unsigned)BKr + row] = 1.0f;
        }
        o++;
      }
    }
  }
}

// ---------------- zero only the invalid tail rows (R13-proven) ----------------
__global__ __launch_bounds__(256) void k_cleanup(float* __restrict__ out, int out_elems){
  unsigned row = blockIdx.x*256u + threadIdx.x;
  if (row >= (unsigned)BKr) return;
  unsigned b = row / Kpad;
  unsigned r = row - b*Kpad;
  if (r < __ldcg(&g_total[b])) return;
  const bool fits = (out_elems >= (int)(10u*(unsigned)BKr));
  if (fits){
    unsigned f = row*5u;
    out[f+0u]=0.f; out[f+1u]=0.f; out[f+2u]=0.f; out[f+3u]=0.f; out[f+4u]=0.f;
    unsigned ioff = 5u*(unsigned)BKr + row*4u;
    *reinterpret_cast<float4*>(out + ioff) = make_float4(0.f,0.f,0.f,0.f);
    out[9u*(unsigned)BKr + row] = 0.f;
  }
}

extern "C" void kernel_launch(void* const* d_in, const int* in_sizes, int n_in,
                              void* d_out, int out_size) {
  const float* cube = (const float*)d_in[0];
  const float* dop  = (const float*)d_in[1];
  float* out = (float*)d_out;

  if ((size_t)out_size > (size_t)BKr*10)
    cudaMemsetAsync(out + (size_t)BKr*10, 0,
                    ((size_t)out_size - (size_t)BKr*10)*sizeof(float));
  else if ((size_t)out_size < (size_t)BKr*10)
    cudaMemsetAsync(out, 0, (size_t)out_size * sizeof(float)); // defensive

  k_zero<<<32,1024>>>();

  dim3 gh(HV_BLOCKS, Bn);
  k_hist1<<<gh,1024>>>(cube);
  k_hist2<<<gh,1024>>>(cube);
  dim3 g3(H3C_BLOCKS, Bn);
  k_hist3c<<<g3,1024>>>();

  dim3 gs(SC_BLOCKS, Bn);
  k_scatter<<<gs,SC_THREADS>>>(cube, dop, out, out_size);
  k_cleanup<<<(BKr+255)/256,256>>>(out, out_size);
}

// round 17
// speedup vs baseline: 1.1112x; 1.1112x over previous
#include <cuda_runtime.h>
#include <stdint.h>

// RadarDopSparseProcessor — exact 0.9-quantile radix select (12b/12b/8b full
// passes, select computed in each pass's last-block tail) + ordered lookback
// stream compaction with fused tail cleanup. 2 CTAs/SM on hist passes.

#define Bn 4
#define Zd 40
#define Yd 320
#define Xd 320
#define Nv (Zd*Yd*Xd)            // 4,096,000
#define Kpad (Nv/10 + 64)        // 409,664
#define BKr (Bn*Kpad)            // 1,638,656
#define VPBATCH (Nv/4)           // 1,024,000 float4 per batch

#define HV_BLOCKS 74
#define VPB 13838                // ceil(1024000/74)
#define SC_BLOCKS 250
#define SC_THREADS 512
#define SENT 0xFFFFFFFFu

__device__ unsigned g_hist1[Bn][4096];
__device__ unsigned g_hist2[Bn][2][4096];
__device__ unsigned g_hist3[Bn][2][256];
__device__ unsigned g_s1[Bn][4];          // selA, remA, selB, remB
__device__ unsigned g_s2[Bn][4];          // sel2A, rem2A, sel2B, rem2B
__device__ float    g_thr[Bn];
__device__ unsigned g_done1[Bn];
__device__ unsigned g_done2[Bn];
__device__ unsigned g_done3[Bn];
__device__ unsigned g_dones[Bn];
__device__ unsigned long long g_part[Bn][SC_BLOCKS];
__device__ unsigned g_total[Bn];

__device__ __forceinline__ unsigned wscan(unsigned v, int lane){
  #pragma unroll
  for (int d=1; d<32; d<<=1){
    unsigned n = __shfl_up_sync(0xFFFFFFFFu, v, d);
    if (lane >= d) v += n;
  }
  return v;
}

__device__ __forceinline__ void qranks(unsigned& R0, unsigned& R1){
  const float QPOS = 0.9f * (float)(Nv-1);
  R0 = (unsigned)floorf(QPOS);
  R1 = (unsigned)ceilf(QPOS); if (R1 > Nv-1) R1 = Nv-1;
}

__global__ __launch_bounds__(1024) void k_zero(){
  int i = blockIdx.x*1024 + threadIdx.x;
  if (i < Bn*4096)      (&g_hist1[0][0])[i] = 0u;
  if (i < Bn*2*4096)    (&g_hist2[0][0][0])[i] = 0u;
  if (i < Bn*2*256)     (&g_hist3[0][0][0])[i] = 0u;
  if (i < Bn*SC_BLOCKS) (&g_part[0][0])[i] = 0ull;
  if (i < Bn){ g_done1[i]=0u; g_done2[i]=0u; g_done3[i]=0u; g_dones[i]=0u; g_total[i]=0u; }
}

// ---- block-collective select over a 4096-bin smem histogram (1024 threads) ----
__device__ void bsel4096(const unsigned* h, unsigned rA, unsigned rB,
                         unsigned* swq, unsigned* res){
  int tid=threadIdx.x, lane=tid&31;
  unsigned l0=h[tid*4+0],l1=h[tid*4+1],l2=h[tid*4+2],l3=h[tid*4+3];
  unsigned sum=l0+l1+l2+l3;
  unsigned inc=wscan(sum,lane);
  if (lane==31) swq[tid>>5]=inc;
  __syncthreads();
  if (tid==0){unsigned run=0; for(int k=0;k<32;k++){unsigned t=swq[k];swq[k]=run;run+=t;}}
  __syncthreads();
  unsigned excl=inc-sum+swq[tid>>5];
  unsigned rr[2]={rA,rB};
  #pragma unroll
  for (int j=0;j<2;j++){
    unsigned r=rr[j];
    if (r!=SENT && r>=excl && r<excl+sum){
      unsigned c=excl; unsigned loc[4]={l0,l1,l2,l3};
      #pragma unroll
      for (int k=0;k<4;k++){
        if (r < c+loc[k]){ res[2*j]=(unsigned)(tid*4+k); res[2*j+1]=r-c; break; }
        c+=loc[k];
      }
    }
  }
  __syncthreads();
}

__device__ void bsel256(const unsigned* h, unsigned rA, unsigned rB,
                        unsigned* swq, unsigned* res){
  int tid=threadIdx.x, lane=tid&31;
  unsigned v=0, inc=0;
  if (tid<256){ v=h[tid]; inc=wscan(v,lane); }
  if (tid<256 && lane==31) swq[tid>>5]=inc;
  __syncthreads();
  if (tid==0){unsigned run=0; for(int k=0;k<8;k++){unsigned t=swq[k];swq[k]=run;run+=t;}}
  __syncthreads();
  if (tid<256){
    unsigned excl=inc-v+swq[tid>>5];
    unsigned rr[2]={rA,rB};
    #pragma unroll
    for (int j=0;j<2;j++){
      unsigned r=rr[j];
      if (r!=SENT && r>=excl && r<excl+v) res[2*j]=(unsigned)tid;
    }
  }
  __syncthreads();
}

// ---- last-block detection (threadFenceReduction pattern) ----
__device__ __forceinline__ bool last_block(unsigned* ctr, unsigned total, bool* sflag){
  __threadfence();
  __syncthreads();
  if (threadIdx.x==0) *sflag = (atomicAdd(ctr,1u) == total-1u);
  __syncthreads();
  return *sflag;
}

// ---------------- pass 1: 12-bit histogram, 2-way replicated smem ----------------
__device__ __forceinline__ void h1a(unsigned* h, float4 a){
  atomicAdd(&h[__float_as_uint(a.x)>>20],1u);
  atomicAdd(&h[__float_as_uint(a.y)>>20],1u);
  atomicAdd(&h[__float_as_uint(a.z)>>20],1u);
  atomicAdd(&h[__float_as_uint(a.w)>>20],1u);
}
__global__ __launch_bounds__(1024) void k_hist1(const float* __restrict__ cube){
  __shared__ unsigned hist[2][4096];
  __shared__ unsigned swq[32];
  __shared__ unsigned sres[4];
  __shared__ bool sflag;
  int b = blockIdx.y, tid = threadIdx.x;
  unsigned* myh = hist[(tid>>5)&1];
  int start = blockIdx.x * VPB;
  int n = min(VPB, VPBATCH - start);
  const float4* p = (const float4*)cube + (size_t)b*VPBATCH + start;
  for (int i=tid;i<8192;i+=1024) (&hist[0][0])[i]=0u;
  __syncthreads();
  int i = tid;
  for (; i + 3072 < n; i += 4096){
    float4 v0=p[i], v1=p[i+1024], v2=p[i+2048], v3=p[i+3072];
    h1a(myh,v0); h1a(myh,v1); h1a(myh,v2); h1a(myh,v3);
  }
  for (; i < n; i += 1024) h1a(myh, p[i]);
  __syncthreads();
  for (int k=tid;k<4096;k+=1024){
    unsigned c=hist[0][k]+hist[1][k];
    if (c) atomicAdd(&g_hist1[b][k], c);
  }
  if (last_block(&g_done1[b], HV_BLOCKS, &sflag)){
    for (int k=tid;k<4096;k+=1024) hist[0][k]=__ldcg(&g_hist1[b][k]);
    __syncthreads();
    unsigned R0,R1; qranks(R0,R1);
    bsel4096(hist[0], R0, R1, swq, sres);
    if (tid<4) g_s1[b][tid]=sres[tid];
  }
}

// ---------------- pass 2: 12-bit mid histogram (bits 19..8), batched loads ----------------
__device__ __forceinline__ void h2a(unsigned* h0, unsigned* h1, unsigned sa, unsigned sb, float4 a){
  float vv[4]={a.x,a.y,a.z,a.w};
  #pragma unroll
  for (int c2=0;c2<4;c2++){
    unsigned u=__float_as_uint(vv[c2]); unsigned t=u>>20;
    if (t==sa) atomicAdd(&h0[(u>>8)&0xFFFu],1u);
    else if (t==sb) atomicAdd(&h1[(u>>8)&0xFFFu],1u);
  }
}
__global__ __launch_bounds__(1024) void k_hist2(const float* __restrict__ cube){
  __shared__ unsigned hist[2][4096];
  __shared__ unsigned swq[32];
  __shared__ unsigned sres[4];
  __shared__ bool sflag;
  int b = blockIdx.y, tid = threadIdx.x;
  unsigned sa=__ldcg(&g_s1[b][0]);
  unsigned sb=__ldcg(&g_s1[b][2]);
  for (int i=tid;i<8192;i+=1024) (&hist[0][0])[i]=0u;
  __syncthreads();
  int start = blockIdx.x * VPB;
  int n = min(VPB, VPBATCH - start);
  const float4* p = (const float4*)cube + (size_t)b*VPBATCH + start;
  int i = tid;
  for (; i + 3072 < n; i += 4096){
    float4 v0=p[i], v1=p[i+1024], v2=p[i+2048], v3=p[i+3072];
    h2a(hist[0],hist[1],sa,sb,v0); h2a(hist[0],hist[1],sa,sb,v1);
    h2a(hist[0],hist[1],sa,sb,v2); h2a(hist[0],hist[1],sa,sb,v3);
  }
  for (; i < n; i += 1024) h2a(hist[0],hist[1],sa,sb,p[i]);
  __syncthreads();
  for (int k=tid;k<8192;k+=1024){
    unsigned c=(&hist[0][0])[k];
    if (c) atomicAdd((&g_hist2[b][0][0])+k, c);
  }
  if (last_block(&g_done2[b], HV_BLOCKS, &sflag)){
    unsigned selA=__ldcg(&g_s1[b][0]), remA=__ldcg(&g_s1[b][1]);
    unsigned selB=__ldcg(&g_s1[b][2]), remB=__ldcg(&g_s1[b][3]);
    unsigned sel2A, rem2A, sel2B, rem2B;
    for (int k=tid;k<4096;k+=1024) hist[0][k]=__ldcg(&g_hist2[b][0][k]);
    __syncthreads();
    if (selA==selB){
      bsel4096(hist[0], remA, remB, swq, sres);
      sel2A=(selA<<12)|sres[0]; rem2A=sres[1];
      sel2B=(selB<<12)|sres[2]; rem2B=sres[3];
    } else {
      bsel4096(hist[0], remA, SENT, swq, sres);
      sel2A=(selA<<12)|sres[0]; rem2A=sres[1];
      __syncthreads();
      for (int k=tid;k<4096;k+=1024) hist[0][k]=__ldcg(&g_hist2[b][1][k]);
      __syncthreads();
      bsel4096(hist[0], SENT, remB, swq, sres);
      sel2B=(selB<<12)|sres[2]; rem2B=sres[3];
    }
    if (tid==0){ g_s2[b][0]=sel2A; g_s2[b][1]=rem2A; g_s2[b][2]=sel2B; g_s2[b][3]=rem2B; }
  }
}

// ---------------- pass 3: 8-bit histogram (bits 7..0), batched loads ----------------
__device__ __forceinline__ void h3a(unsigned* h8, unsigned p0, unsigned p1, float4 a){
  float vv[4]={a.x,a.y,a.z,a.w};
  #pragma unroll
  for (int c2=0;c2<4;c2++){
    unsigned u=__float_as_uint(vv[c2]); unsigned pre=u>>8;
    if (pre==p0) atomicAdd(&h8[u&0xFFu],1u);
    else if (pre==p1) atomicAdd(&h8[256u+(u&0xFFu)],1u);
  }
}
__global__ __launch_bounds__(1024) void k_hist3(const float* __restrict__ cube){
  __shared__ unsigned h8[512];
  __shared__ unsigned swq[32];
  __shared__ unsigned sres[4];
  __shared__ bool sflag;
  int b = blockIdx.y, tid = threadIdx.x;
  unsigned p0=__ldcg(&g_s2[b][0]);
  unsigned p1=__ldcg(&g_s2[b][2]);
  for (int i=tid;i<512;i+=1024) h8[i]=0u;
  __syncthreads();
  int start = blockIdx.x * VPB;
  int n = min(VPB, VPBATCH - start);
  const float4* p = (const float4*)cube + (size_t)b*VPBATCH + start;
  int i = tid;
  for (; i + 3072 < n; i += 4096){
    float4 v0=p[i], v1=p[i+1024], v2=p[i+2048], v3=p[i+3072];
    h3a(h8,p0,p1,v0); h3a(h8,p0,p1,v1); h3a(h8,p0,p1,v2); h3a(h8,p0,p1,v3);
  }
  for (; i < n; i += 1024) h3a(h8,p0,p1,p[i]);
  __syncthreads();
  for (int k=tid;k<512;k+=1024){
    unsigned c=h8[k];
    if (c) atomicAdd((&g_hist3[b][0][0])+k, c);
  }
  if (last_block(&g_done3[b], HV_BLOCKS, &sflag)){
    unsigned sel2A=__ldcg(&g_s2[b][0]), rem2A=__ldcg(&g_s2[b][1]);
    unsigned sel2B=__ldcg(&g_s2[b][2]), rem2B=__ldcg(&g_s2[b][3]);
    for (int k=tid;k<512;k+=1024) h8[k]=__ldcg((&g_hist3[b][0][0])+k);
    __syncthreads();
    unsigned binA, binB;
    if (sel2A==sel2B){
      bsel256(&h8[0], rem2A, rem2B, swq, sres);
      binA=sres[0]; binB=sres[2];
    } else {
      bsel256(&h8[0], rem2A, SENT, swq, sres);
      binA=sres[0];
      __syncthreads();
      bsel256(&h8[256], SENT, rem2B, swq, sres);
      binB=sres[2];
    }
    if (tid==0){
      const float QPOS = 0.9f * (float)(Nv-1);
      float frac = QPOS - floorf(QPOS);
      float va=__uint_as_float((sel2A<<8)|binA);
      float vb=__uint_as_float((sel2B<<8)|binB);
      g_thr[b]=va*(1.0f-frac)+vb*frac;
    }
  }
}

// ---------------- fused compaction: lookback (R13-proven) + fused tail cleanup ----------------
__global__ __launch_bounds__(SC_THREADS) void k_scatter(const float* __restrict__ cube,
                                                        const float* __restrict__ dop,
                                                        float* __restrict__ out, int out_elems){
  __shared__ unsigned warpsum[16];
  __shared__ unsigned warpexcl[16];
  __shared__ unsigned s_agg;
  __shared__ unsigned s_gexcl;
  __shared__ bool sflag;
  int b = blockIdx.y;
  float thr = g_thr[b];
  int tid = threadIdx.x, lane = tid & 31, wid = tid >> 5;

  unsigned gvec0 = (unsigned)blockIdx.x*4096u + (unsigned)wid*256u;
  const float4* p = (const float4*)cube + (size_t)b*VPBATCH + gvec0;

  float4 v[8];
  #pragma unroll
  for (int j=0;j<8;j++) v[j] = p[j*32 + lane];

  unsigned esc[8], gbase[8];
  unsigned run = 0;
  #pragma unroll
  for (int j=0;j<8;j++){
    unsigned c = (v[j].x>thr)+(v[j].y>thr)+(v[j].z>thr)+(v[j].w>thr);
    unsigned inc = c;
    #pragma unroll
    for (int d=1;d<32;d<<=1){ unsigned t=__shfl_up_sync(0xFFFFFFFFu,inc,d); if (lane>=d) inc+=t; }
    esc[j] = inc - c;
    gbase[j] = run;
    run += __shfl_sync(0xFFFFFFFFu, inc, 31);
  }
  if (lane==0) warpsum[wid] = run;
  __syncthreads();
  if (tid==0){
    unsigned acc=0;
    for (int k=0;k<16;k++){ unsigned t=warpsum[k]; warpexcl[k]=acc; acc+=t; }
    s_agg = acc;
  }
  __syncthreads();

  if (wid==0){
    unsigned agg = s_agg;
    unsigned excl = 0;
    int bx = blockIdx.x;
    if (bx == 0){
      if (lane==0) atomicExch(&g_part[b][0], (2ull<<62) | (unsigned long long)agg);
    } else {
      if (lane==0) atomicExch(&g_part[b][bx], (1ull<<62) | (unsigned long long)agg);
      unsigned running = 0;
      int j = bx - 1;
      while (true){
        int idx = j - lane;
        unsigned long long w; unsigned st;
        do {
          w = (idx >= 0) ? atomicAdd(&g_part[b][idx], 0ull) : (2ull<<62);
          st = (unsigned)(w>>62);
        } while (__any_sync(0xFFFFFFFFu, st==0u));
        unsigned val = (unsigned)(w & 0xFFFFFFFFull);
        unsigned bal = __ballot_sync(0xFFFFFFFFu, st==2u);
        if (bal){
          int f = __ffs(bal)-1;
          unsigned contrib = (lane<=f) ? val : 0u;
          #pragma unroll
          for (int d=16;d>0;d>>=1) contrib += __shfl_down_sync(0xFFFFFFFFu,contrib,d);
          running += __shfl_sync(0xFFFFFFFFu, contrib, 0);
          break;
        } else {
          unsigned contrib = val;
          #pragma unroll
          for (int d=16;d>0;d>>=1) contrib += __shfl_down_sync(0xFFFFFFFFu,contrib,d);
          running += __shfl_sync(0xFFFFFFFFu, contrib, 0);
          j -= 32;
        }
      }
      excl = running;
      if (lane==0) atomicExch(&g_part[b][bx], (2ull<<62) | (unsigned long long)(excl+agg));
    }
    if (lane==0){
      s_gexcl = excl;
      if (bx == SC_BLOCKS-1) g_total[b] = excl + agg;
    }
  }
  __syncthreads();

  unsigned warpbase = s_gexcl + warpexcl[wid];
  const float* dopb = dop + (size_t)b*Nv;
  const bool fits = (out_elems >= (int)(10u*(unsigned)BKr));
  #pragma unroll
  for (int j=0;j<8;j++){
    unsigned o = warpbase + gbase[j] + esc[j];
    unsigned gvec = gvec0 + (unsigned)j*32u + (unsigned)lane;
    float vals[4] = {v[j].x, v[j].y, v[j].z, v[j].w};
    float dv[4];
    #pragma unroll
    for (int c2=0;c2<4;c2++){
      if (vals[c2] > thr) dv[c2] = __ldg(&dopb[gvec*4u + (unsigned)c2]);
    }
    #pragma unroll
    for (int c2=0;c2<4;c2++){
      if (vals[c2] > thr){
        unsigned gidx = gvec*4u + (unsigned)c2;
        unsigned z = gidx/(Yd*Xd);
        unsigned rem = gidx - z*(Yd*Xd);
        unsigned y = rem/Xd;
        unsigned x = rem - y*Xd;
        unsigned row = (unsigned)b*Kpad + o;
        if (fits){
          unsigned f = row*5u;
          out[f+0u] = ((float)x/320.0f)*72.0f;
          out[f+1u] = ((float)y/320.0f)*32.0f;
          out[f+2u] = ((float)z/40.0f)*8.0f;
          out[f+3u] = vals[c2] / 10000000000000.0f;
          out[f+4u] = dv[c2] - 1.9326f;
          unsigned ioff = 5u*(unsigned)BKr + row*4u;
          float4 iv = make_float4((float)b,(float)z,(float)y,(float)x);
          *reinterpret_cast<float4*>(out + ioff) = iv;   // 16B-aligned
          out[9u*(unsigned)BKr + row] = 1.0f;
        }
        o++;
      }
    }
  }

  // ---- fused cleanup: last block per batch zeroes the invalid tail rows ----
  if (last_block(&g_dones[b], SC_BLOCKS, &sflag)){
    unsigned total = __ldcg(&g_total[b]);
    if (fits){
      for (unsigned r = total + (unsigned)tid; r < (unsigned)Kpad; r += SC_THREADS){
        unsigned row = (unsigned)b*Kpad + r;
        unsigned f = row*5u;
        out[f+0u]=0.f; out[f+1u]=0.f; out[f+2u]=0.f; out[f+3u]=0.f; out[f+4u]=0.f;
        unsigned ioff = 5u*(unsigned)BKr + row*4u;
        *reinterpret_cast<float4*>(out + ioff) = make_float4(0.f,0.f,0.f,0.f);
        out[9u*(unsigned)BKr + row] = 0.f;
      }
    }
  }
}

extern "C" void kernel_launch(void* const* d_in, const int* in_sizes, int n_in,
                              void* d_out, int out_size) {
  const float* cube = (const float*)d_in[0];
  const float* dop  = (const float*)d_in[1];
  float* out = (float*)d_out;

  if ((size_t)out_size > (size_t)BKr*10)
    cudaMemsetAsync(out + (size_t)BKr*10, 0,
                    ((size_t)out_size - (size_t)BKr*10)*sizeof(float));
  else if ((size_t)out_size < (size_t)BKr*10)
    cudaMemsetAsync(out, 0, (size_t)out_size * sizeof(float)); // defensive

  k_zero<<<32,1024>>>();

  dim3 gh(HV_BLOCKS, Bn);
  k_hist1<<<gh,1024>>>(cube);
  k_hist2<<<gh,1024>>>(cube);
  k_hist3<<<gh,1024>>>(cube);

  dim3 gs(SC_BLOCKS, Bn);
  k_scatter<<<gs,SC_THREADS>>>(cube, dop, out, out_size);
}